// round 1
// baseline (speedup 1.0000x reference)
#include <cuda_runtime.h>
#include <math.h>

// Problem constants
#define T_ 256
#define B_ 128
#define F_ 1024
#define U_ 512
#define G_ 2048   // 4*U
#define CODES_ 1024

// Scratch in __device__ globals (no runtime allocation allowed)
__device__ float g_xz[(long long)T_ * B_ * G_];     // 256 MiB: input projections
__device__ float g_hseq[(long long)T_ * B_ * U_];   // 64 MiB: masked hidden states
__device__ float g_hbuf[2][B_ * U_];                // ping-pong h
__device__ float g_c[B_ * U_];                      // cell state

// ---------------------------------------------------------------------------
// init: zero h0 and c
// ---------------------------------------------------------------------------
__global__ void init_state_kernel() {
    int i = blockIdx.x * blockDim.x + threadIdx.x;
    if (i < B_ * U_) {
        g_hbuf[0][i] = 0.f;
        g_c[i] = 0.f;
    }
}

// ---------------------------------------------------------------------------
// SGEMM: C = A @ B + bias  (optionally ReLU). 128x128 tile, BK=8, 8x8/thread.
// MODE 0: A = Ap (x),     C = g_xz,  no ReLU   (xz projection)
// MODE 1: A = g_hseq,     C = Cp,    ReLU      (dense logits)
// Requires M%128==0, N%128==0, K%8==0 (true for our shapes).
// ---------------------------------------------------------------------------
template <int MODE>
__global__ __launch_bounds__(256) void sgemm_bias_kernel(
    const float* __restrict__ Ap, const float* __restrict__ Bm,
    const float* __restrict__ bias, float* __restrict__ Cp,
    int M, int N, int K)
{
    constexpr int BM = 128, BN = 128, BK = 8, TM = 8, TN = 8;
    const float* A = (MODE == 0) ? Ap : g_hseq;
    float* C = (MODE == 0) ? g_xz : Cp;

    __shared__ float As[BK][BM];
    __shared__ float Bs[BK][BN];

    const int tid = threadIdx.x;
    const int bx = blockIdx.x, by = blockIdx.y;
    const int trow = tid / 16;   // 0..15
    const int tcol = tid % 16;   // 0..15

    const float* Ab = A + (long long)by * BM * K;
    const float* Bb = Bm + (long long)bx * BN;

    float acc[TM][TN];
#pragma unroll
    for (int i = 0; i < TM; i++)
#pragma unroll
        for (int j = 0; j < TN; j++) acc[i][j] = 0.f;

    const int aRow = tid >> 1;          // 0..127
    const int aCol = (tid & 1) * 4;     // 0 or 4
    const int bRow = tid >> 5;          // 0..7
    const int bCol = (tid & 31) * 4;    // 0..124

    for (int k0 = 0; k0 < K; k0 += BK) {
        float4 av = *reinterpret_cast<const float4*>(Ab + (long long)aRow * K + k0 + aCol);
        As[aCol + 0][aRow] = av.x;
        As[aCol + 1][aRow] = av.y;
        As[aCol + 2][aRow] = av.z;
        As[aCol + 3][aRow] = av.w;
        float4 bv = *reinterpret_cast<const float4*>(Bb + (long long)(k0 + bRow) * N + bCol);
        *reinterpret_cast<float4*>(&Bs[bRow][bCol]) = bv;
        __syncthreads();

#pragma unroll
        for (int kk = 0; kk < BK; kk++) {
            float ar[TM], br[TN];
#pragma unroll
            for (int i = 0; i < TM; i++) ar[i] = As[kk][trow * TM + i];
#pragma unroll
            for (int j = 0; j < TN; j++) br[j] = Bs[kk][tcol * TN + j];
#pragma unroll
            for (int i = 0; i < TM; i++)
#pragma unroll
                for (int j = 0; j < TN; j++)
                    acc[i][j] = fmaf(ar[i], br[j], acc[i][j]);
        }
        __syncthreads();
    }

#pragma unroll
    for (int i = 0; i < TM; i++) {
        long long row = (long long)by * BM + trow * TM + i;
#pragma unroll
        for (int j = 0; j < TN; j += 4) {
            int col = bx * BN + tcol * TN + j;
            float4 bz = *reinterpret_cast<const float4*>(bias + col);
            float4 v;
            v.x = acc[i][j + 0] + bz.x;
            v.y = acc[i][j + 1] + bz.y;
            v.z = acc[i][j + 2] + bz.z;
            v.w = acc[i][j + 3] + bz.w;
            if (MODE == 1) {
                v.x = fmaxf(v.x, 0.f); v.y = fmaxf(v.y, 0.f);
                v.z = fmaxf(v.z, 0.f); v.w = fmaxf(v.w, 0.f);
            }
            *reinterpret_cast<float4*>(C + row * N + col) = v;
        }
    }
}

// ---------------------------------------------------------------------------
// One LSTM step, fused: z = xz[t] + h_in @ W_rec; gates; c,h update; masked h.
// Grid: (U/16, B/16), 256 threads. Each thread owns one (b,u), 4 gate accs.
// h ping-pongs between g_hbuf[0] and g_hbuf[1] to avoid read/write races.
// ---------------------------------------------------------------------------
__global__ __launch_bounds__(256) void lstm_step_kernel(
    int t, const float* __restrict__ W_rec, const float* __restrict__ mask)
{
    constexpr int BB = 16, KC = 64;
    __shared__ float sh[BB][KC];

    const float* xz_t   = g_xz + (long long)t * B_ * G_;
    const float* h_in   = g_hbuf[t & 1];
    float*       h_out  = g_hbuf[(t + 1) & 1];
    float*       hseq_t = g_hseq + (long long)t * B_ * U_;
    const float* mask_t = mask + (long long)t * B_;

    const int tid = threadIdx.x;
    const int tx = tid & 15;   // u within tile
    const int ty = tid >> 4;   // b within tile
    const int u0 = blockIdx.x * 16;
    const int b0 = blockIdx.y * BB;
    const int b = b0 + ty;
    const int u = u0 + tx;

    const long long zb = (long long)b * G_ + u;
    float acc0 = xz_t[zb];
    float acc1 = xz_t[zb + U_];
    float acc2 = xz_t[zb + 2 * U_];
    float acc3 = xz_t[zb + 3 * U_];

    const int lr = tid >> 4;         // 0..15
    const int lc = (tid & 15) * 4;   // 0..60

    for (int k0 = 0; k0 < U_; k0 += KC) {
        float4 hv = *reinterpret_cast<const float4*>(
            h_in + (long long)(b0 + lr) * U_ + k0 + lc);
        *reinterpret_cast<float4*>(&sh[lr][lc]) = hv;
        __syncthreads();
#pragma unroll 8
        for (int kk = 0; kk < KC; kk++) {
            float hk = sh[ty][kk];
            const float* w = W_rec + (long long)(k0 + kk) * G_ + u;
            acc0 = fmaf(hk, w[0],        acc0);
            acc1 = fmaf(hk, w[U_],       acc1);
            acc2 = fmaf(hk, w[2 * U_],   acc2);
            acc3 = fmaf(hk, w[3 * U_],   acc3);
        }
        __syncthreads();
    }

    float ig = 1.f / (1.f + expf(-acc0));
    float fg = 1.f / (1.f + expf(-acc1));
    float gg = tanhf(acc2);
    float og = 1.f / (1.f + expf(-acc3));

    const int idx = b * U_ + u;
    float cn = fg * g_c[idx] + ig * gg;
    g_c[idx] = cn;
    float hn = og * tanhf(cn);
    h_out[idx] = hn;
    hseq_t[idx] = hn * mask_t[b];
}

// ---------------------------------------------------------------------------
// In-place softmax over rows of 1024 (post-ReLU logits). One block per row.
// ---------------------------------------------------------------------------
__global__ __launch_bounds__(256) void softmax1024_kernel(float* __restrict__ data)
{
    __shared__ float red[32];
    long long row = blockIdx.x;
    float* p = data + row * CODES_;
    int tid = threadIdx.x;

    float4 v = *reinterpret_cast<const float4*>(p + tid * 4);

    // block max
    float m = fmaxf(fmaxf(v.x, v.y), fmaxf(v.z, v.w));
#pragma unroll
    for (int o = 16; o > 0; o >>= 1) m = fmaxf(m, __shfl_xor_sync(0xffffffffu, m, o));
    if ((tid & 31) == 0) red[tid >> 5] = m;
    __syncthreads();
    if (tid < 8) {
        float tt = red[tid];
#pragma unroll
        for (int o = 4; o > 0; o >>= 1) tt = fmaxf(tt, __shfl_xor_sync(0xffu, tt, o));
        if (tid == 0) red[0] = tt;
    }
    __syncthreads();
    m = red[0];
    __syncthreads();  // everyone read red[0] before reuse

    v.x = expf(v.x - m); v.y = expf(v.y - m);
    v.z = expf(v.z - m); v.w = expf(v.w - m);
    float s = v.x + v.y + v.z + v.w;
#pragma unroll
    for (int o = 16; o > 0; o >>= 1) s += __shfl_xor_sync(0xffffffffu, s, o);
    if ((tid & 31) == 0) red[tid >> 5] = s;
    __syncthreads();
    if (tid < 8) {
        float tt = red[tid];
#pragma unroll
        for (int o = 4; o > 0; o >>= 1) tt += __shfl_xor_sync(0xffu, tt, o);
        if (tid == 0) red[0] = tt;
    }
    __syncthreads();
    float inv = 1.f / red[0];

    v.x *= inv; v.y *= inv; v.z *= inv; v.w *= inv;
    *reinterpret_cast<float4*>(p + tid * 4) = v;
}

// ---------------------------------------------------------------------------
// Launch
// ---------------------------------------------------------------------------
extern "C" void kernel_launch(void* const* d_in, const int* in_sizes, int n_in,
                              void* d_out, int out_size)
{
    const float* x       = (const float*)d_in[0];  // [T,B,F]
    const float* mask    = (const float*)d_in[1];  // [T,B]
    const float* W_in    = (const float*)d_in[2];  // [F,4U]
    const float* W_rec   = (const float*)d_in[3];  // [U,4U]
    const float* b_lstm  = (const float*)d_in[4];  // [4U]
    const float* W_dense = (const float*)d_in[5];  // [U,CODES]
    const float* b_dense = (const float*)d_in[6];  // [CODES]
    float* out = (float*)d_out;                    // [T,B,CODES]

    (void)in_sizes; (void)n_in; (void)out_size;

    // 1) zero initial state
    init_state_kernel<<<(B_ * U_ + 255) / 256, 256>>>();

    // 2) xz = x @ W_in + b_lstm : [T*B, 4U]
    {
        dim3 grid(G_ / 128, (T_ * B_) / 128);
        sgemm_bias_kernel<0><<<grid, 256>>>(x, W_in, b_lstm, nullptr,
                                            T_ * B_, G_, F_);
    }

    // 3) sequential LSTM steps
    {
        dim3 grid(U_ / 16, B_ / 16);
        for (int t = 0; t < T_; t++) {
            lstm_step_kernel<<<grid, 256>>>(t, W_rec, mask);
        }
    }

    // 4) logits = relu(hseq_masked @ W_dense + b_dense) -> d_out
    {
        dim3 grid(CODES_ / 128, (T_ * B_) / 128);
        sgemm_bias_kernel<1><<<grid, 256>>>(nullptr, W_dense, b_dense, out,
                                            T_ * B_, CODES_, U_);
    }

    // 5) softmax in place on d_out
    softmax1024_kernel<<<T_ * B_, 256>>>(out);
}

// round 6
// speedup vs baseline: 2.2670x; 2.2670x over previous
#include <cuda_runtime.h>
#include <math.h>

// Problem constants
#define T_ 256
#define B_ 128
#define F_ 1024
#define U_ 512
#define G_ 2048   // 4*U
#define CODES_ 1024

// Persistent-LSTM config
#define NBLK 128          // persistent blocks (<=148 SMs, 1 per SM -> co-resident)
#define NU 4              // units owned per block (NBLK*NU == U_)
#define KC 128            // k-chunk staged in SMEM
#define PS 132            // padded row stride (floats) for h chunk

// Scratch in __device__ globals (no runtime allocation allowed)
__device__ float g_xz[(long long)T_ * B_ * G_];     // 256 MiB: input projections
__device__ float g_hseq[(long long)T_ * B_ * U_];   // 64 MiB: masked hidden states
__device__ float g_h[2][B_ * U_];                   // ping-pong h (global, cross-block)
__device__ unsigned g_barcnt;                       // sw grid barrier counter

__device__ __forceinline__ unsigned smem_u32(const void* p) {
    return (unsigned)__cvta_generic_to_shared(p);
}

// ---------------------------------------------------------------------------
// init: zero barrier counter (fresh every launch / graph replay)
// ---------------------------------------------------------------------------
__global__ void init_kernel() {
    if (blockIdx.x == 0 && threadIdx.x == 0) g_barcnt = 0u;
}

// ---------------------------------------------------------------------------
// Persistent LSTM: all 256 timesteps in one kernel. (UNCHANGED from R2-R4.)
// Block bx owns units u in [bx*NU, bx*NU+NU). Weights for those units live in
// SMEM for the whole sequence. Cell state in registers. h exchanged through
// global ping-pong buffers with a software grid barrier per step; h staged
// into SMEM via double-buffered cp.async chunks.
// ---------------------------------------------------------------------------
__global__ void __launch_bounds__(256, 1)
lstm_persistent_kernel(const float* __restrict__ W_rec,
                       const float* __restrict__ mask)
{
    extern __shared__ char smem_raw[];
    float4* w_s = (float4*)smem_raw;                       // 512*NU float4 = 32KB
    float*  sh_h = (float*)(smem_raw + 512 * NU * 16);     // 2 * 128*PS floats

    const int tid = threadIdx.x;
    const int ul  = tid & (NU - 1);
    const int bp  = tid >> 2;         // 0..63
    const int b0  = bp * 2;
    const int b1  = bp * 2 + 1;
    const int u   = blockIdx.x * NU + ul;

    // One-time: gather this block's weight slice into SMEM as float4 (i,f,g,o)
    for (int idx = tid; idx < 512 * NU; idx += 256) {
        int k  = idx >> 2;
        int uu = blockIdx.x * NU + (idx & (NU - 1));
        const float* wr = W_rec + (long long)k * G_ + uu;
        float4 wv;
        wv.x = wr[0];
        wv.y = wr[U_];
        wv.z = wr[2 * U_];
        wv.w = wr[3 * U_];
        w_s[idx] = wv;
    }
    __syncthreads();

    float c0 = 0.f, c1 = 0.f;

    for (int t = 0; t < T_; t++) {
        const int p = t & 1;
        const float* __restrict__ h_in  = g_h[p];
        float* __restrict__       h_out = g_h[p ^ 1];
        const float* __restrict__ xz_t  = g_xz + (long long)t * B_ * G_;

        // accumulators init = xz (input projection + bias, precomputed)
        float a0, a1, a2, a3, a4, a5, a6, a7;
        {
            const long long base0 = (long long)b0 * G_ + u;
            const long long base1 = (long long)b1 * G_ + u;
            a0 = xz_t[base0];
            a1 = xz_t[base0 + U_];
            a2 = xz_t[base0 + 2 * U_];
            a3 = xz_t[base0 + 3 * U_];
            a4 = xz_t[base1];
            a5 = xz_t[base1 + U_];
            a6 = xz_t[base1 + 2 * U_];
            a7 = xz_t[base1 + 3 * U_];
        }

        if (t > 0) {
            // ---- prologue: async-load chunk 0 into buf 0 ----
            {
                float* dst = sh_h;  // buf 0
#pragma unroll
                for (int i = 0; i < 16; i++) {
                    int idx = tid + i * 256;        // 0..4095
                    int row = idx >> 5;             // 0..127
                    int ch  = idx & 31;             // 0..31 (16B chunks)
                    unsigned sa = smem_u32(dst + row * PS + ch * 4);
                    const float* gs = h_in + row * U_ + ch * 4;
                    asm volatile("cp.async.cg.shared.global [%0], [%1], 16;\n"
                                 :: "r"(sa), "l"(gs));
                }
                asm volatile("cp.async.commit_group;\n");
            }

#pragma unroll
            for (int cc = 0; cc < 4; cc++) {
                if (cc < 3) {
                    // issue next chunk into the other buffer
                    float* dst = sh_h + ((cc + 1) & 1) * (B_ * PS);
                    const int k0n = (cc + 1) * KC;
#pragma unroll
                    for (int i = 0; i < 16; i++) {
                        int idx = tid + i * 256;
                        int row = idx >> 5;
                        int ch  = idx & 31;
                        unsigned sa = smem_u32(dst + row * PS + ch * 4);
                        const float* gs = h_in + row * U_ + k0n + ch * 4;
                        asm volatile("cp.async.cg.shared.global [%0], [%1], 16;\n"
                                     :: "r"(sa), "l"(gs));
                    }
                    asm volatile("cp.async.commit_group;\n");
                    asm volatile("cp.async.wait_group 1;\n" ::: "memory");
                } else {
                    asm volatile("cp.async.wait_group 0;\n" ::: "memory");
                }
                __syncthreads();

                // ---- compute on current chunk ----
                const float* shb = sh_h + (cc & 1) * (B_ * PS);
                const int k0 = cc * KC;
#pragma unroll 4
                for (int kk = 0; kk < KC; kk++) {
                    float h0 = shb[b0 * PS + kk];
                    float h1 = shb[b1 * PS + kk];
                    float4 wv = w_s[(k0 + kk) * NU + ul];
                    a0 = fmaf(h0, wv.x, a0);
                    a1 = fmaf(h0, wv.y, a1);
                    a2 = fmaf(h0, wv.z, a2);
                    a3 = fmaf(h0, wv.w, a3);
                    a4 = fmaf(h1, wv.x, a4);
                    a5 = fmaf(h1, wv.y, a5);
                    a6 = fmaf(h1, wv.z, a6);
                    a7 = fmaf(h1, wv.w, a7);
                }
                __syncthreads();
            }
        }

        // ---- gates + state update (c in registers) ----
        float ig0 = 1.f / (1.f + expf(-a0));
        float fg0 = 1.f / (1.f + expf(-a1));
        float gg0 = tanhf(a2);
        float og0 = 1.f / (1.f + expf(-a3));
        c0 = fg0 * c0 + ig0 * gg0;
        float h0v = og0 * tanhf(c0);

        float ig1 = 1.f / (1.f + expf(-a4));
        float fg1 = 1.f / (1.f + expf(-a5));
        float gg1 = tanhf(a6);
        float og1 = 1.f / (1.f + expf(-a7));
        c1 = fg1 * c1 + ig1 * gg1;
        float h1v = og1 * tanhf(c1);

        h_out[b0 * U_ + u] = h0v;
        h_out[b1 * U_ + u] = h1v;

        float m0 = mask[t * B_ + b0];
        float m1 = mask[t * B_ + b1];
        float* hs = g_hseq + (long long)t * B_ * U_;
        hs[b0 * U_ + u] = h0v * m0;
        hs[b1 * U_ + u] = h1v * m1;

        // ---- software grid barrier (skip after final step) ----
        if (t < T_ - 1) {
            __threadfence();          // make this thread's h stores visible
            __syncthreads();          // all threads of block fenced + arrived
            if (tid == 0) {
                atomicAdd(&g_barcnt, 1u);
                const unsigned target = (unsigned)(t + 1) * (unsigned)gridDim.x;
                while (*((volatile unsigned*)&g_barcnt) < target) { }
                __threadfence();      // acquire before next step's reads
            }
            __syncthreads();
        }
    }
}

// ---------------------------------------------------------------------------
// Double-buffered SGEMM: C = A @ B + bias (optionally ReLU).
// 128x128 tile, BK=16, 8x8/thread, cp.async for B, register-prefetch for A.
// MODE 0: A = Ap (x),  C = g_xz,  no ReLU   (xz projection)
// MODE 1: A = g_hseq,  C = Cp,    ReLU      (dense logits)
// Requires M%128==0, N%128==0, K%16==0 (true for our shapes).
// ---------------------------------------------------------------------------
template <int MODE>
__global__ __launch_bounds__(256) void sgemm_db_kernel(
    const float* __restrict__ Ap, const float* __restrict__ Bm,
    const float* __restrict__ bias, float* __restrict__ Cp,
    int M, int N, int K)
{
    constexpr int BM = 128, BN = 128, BK = 16, TM = 8, TN = 8;
    const float* A = (MODE == 0) ? Ap : g_hseq;
    float* C = (MODE == 0) ? g_xz : Cp;

    __shared__ float As[2][BK][BM];   // transposed A tile
    __shared__ float Bs[2][BK][BN];

    const int tid = threadIdx.x;
    const int bx = blockIdx.x, by = blockIdx.y;
    const int trow = tid / 16;   // 0..15
    const int tcol = tid % 16;   // 0..15

    const float* Ab = A + (long long)by * BM * K;
    const float* Bb = Bm + (long long)bx * BN;

    float acc[TM][TN];
#pragma unroll
    for (int i = 0; i < TM; i++)
#pragma unroll
        for (int j = 0; j < TN; j++) acc[i][j] = 0.f;

    // A-load mapping: 512 float4 per ktile, 2 per thread
    const int ar0 = (tid + 0)   >> 2;          // row 0..127
    const int ac0 = ((tid + 0)  & 3) * 4;      // col offset 0,4,8,12
    const int ar1 = (tid + 256) >> 2;
    const int ac1 = ((tid + 256) & 3) * 4;
    // B-load mapping: 512 float4 per ktile, 2 per thread
    const int br0 = (tid + 0)   >> 5;          // row 0..15
    const int bc0 = ((tid + 0)  & 31) * 4;     // col 0..124
    const int br1 = (tid + 256) >> 5;
    const int bc1 = ((tid + 256) & 31) * 4;

    float4 aReg0, aReg1;

    // ---- prologue: k-tile 0 ----
    aReg0 = *reinterpret_cast<const float4*>(Ab + (long long)ar0 * K + ac0);
    aReg1 = *reinterpret_cast<const float4*>(Ab + (long long)ar1 * K + ac1);
    {
        unsigned s0 = smem_u32(&Bs[0][br0][bc0]);
        const float* g0 = Bb + (long long)br0 * N + bc0;
        asm volatile("cp.async.cg.shared.global [%0], [%1], 16;\n" :: "r"(s0), "l"(g0));
        unsigned s1 = smem_u32(&Bs[0][br1][bc1]);
        const float* g1 = Bb + (long long)br1 * N + bc1;
        asm volatile("cp.async.cg.shared.global [%0], [%1], 16;\n" :: "r"(s1), "l"(g1));
        asm volatile("cp.async.commit_group;\n");
    }
    As[0][ac0 + 0][ar0] = aReg0.x;
    As[0][ac0 + 1][ar0] = aReg0.y;
    As[0][ac0 + 2][ar0] = aReg0.z;
    As[0][ac0 + 3][ar0] = aReg0.w;
    As[0][ac1 + 0][ar1] = aReg1.x;
    As[0][ac1 + 1][ar1] = aReg1.y;
    As[0][ac1 + 2][ar1] = aReg1.z;
    As[0][ac1 + 3][ar1] = aReg1.w;
    asm volatile("cp.async.wait_group 0;\n" ::: "memory");
    __syncthreads();

    const int NT = K / BK;
    for (int kt = 0; kt < NT; kt++) {
        const int cur = kt & 1;
        const int nxt = cur ^ 1;

        if (kt + 1 < NT) {
            const int k0 = (kt + 1) * BK;
            aReg0 = *reinterpret_cast<const float4*>(Ab + (long long)ar0 * K + k0 + ac0);
            aReg1 = *reinterpret_cast<const float4*>(Ab + (long long)ar1 * K + k0 + ac1);
            unsigned s0 = smem_u32(&Bs[nxt][br0][bc0]);
            const float* g0 = Bb + (long long)(k0 + br0) * N + bc0;
            asm volatile("cp.async.cg.shared.global [%0], [%1], 16;\n" :: "r"(s0), "l"(g0));
            unsigned s1 = smem_u32(&Bs[nxt][br1][bc1]);
            const float* g1 = Bb + (long long)(k0 + br1) * N + bc1;
            asm volatile("cp.async.cg.shared.global [%0], [%1], 16;\n" :: "r"(s1), "l"(g1));
            asm volatile("cp.async.commit_group;\n");
        }

        // ---- compute on current buffers ----
#pragma unroll
        for (int kk = 0; kk < BK; kk++) {
            float ar[TM], br[TN];
#pragma unroll
            for (int i = 0; i < TM; i++) ar[i] = As[cur][kk][trow * TM + i];
#pragma unroll
            for (int j = 0; j < TN; j++) br[j] = Bs[cur][kk][tcol * TN + j];
#pragma unroll
            for (int i = 0; i < TM; i++)
#pragma unroll
                for (int j = 0; j < TN; j++)
                    acc[i][j] = fmaf(ar[i], br[j], acc[i][j]);
        }

        if (kt + 1 < NT) {
            As[nxt][ac0 + 0][ar0] = aReg0.x;
            As[nxt][ac0 + 1][ar0] = aReg0.y;
            As[nxt][ac0 + 2][ar0] = aReg0.z;
            As[nxt][ac0 + 3][ar0] = aReg0.w;
            As[nxt][ac1 + 0][ar1] = aReg1.x;
            As[nxt][ac1 + 1][ar1] = aReg1.y;
            As[nxt][ac1 + 2][ar1] = aReg1.z;
            As[nxt][ac1 + 3][ar1] = aReg1.w;
            asm volatile("cp.async.wait_group 0;\n" ::: "memory");
            __syncthreads();
        }
    }

#pragma unroll
    for (int i = 0; i < TM; i++) {
        long long row = (long long)by * BM + trow * TM + i;
#pragma unroll
        for (int j = 0; j < TN; j += 4) {
            int col = bx * BN + tcol * TN + j;
            float4 bz = *reinterpret_cast<const float4*>(bias + col);
            float4 v;
            v.x = acc[i][j + 0] + bz.x;
            v.y = acc[i][j + 1] + bz.y;
            v.z = acc[i][j + 2] + bz.z;
            v.w = acc[i][j + 3] + bz.w;
            if (MODE == 1) {
                v.x = fmaxf(v.x, 0.f); v.y = fmaxf(v.y, 0.f);
                v.z = fmaxf(v.z, 0.f); v.w = fmaxf(v.w, 0.f);
            }
            *reinterpret_cast<float4*>(C + row * N + col) = v;
        }
    }
}

// ---------------------------------------------------------------------------
// In-place softmax over rows of 1024 (post-ReLU logits). One block per row.
// ---------------------------------------------------------------------------
__global__ __launch_bounds__(256) void softmax1024_kernel(float* __restrict__ data)
{
    __shared__ float red[32];
    long long row = blockIdx.x;
    float* p = data + row * CODES_;
    int tid = threadIdx.x;

    float4 v = *reinterpret_cast<const float4*>(p + tid * 4);

    float m = fmaxf(fmaxf(v.x, v.y), fmaxf(v.z, v.w));
#pragma unroll
    for (int o = 16; o > 0; o >>= 1) m = fmaxf(m, __shfl_xor_sync(0xffffffffu, m, o));
    if ((tid & 31) == 0) red[tid >> 5] = m;
    __syncthreads();
    if (tid < 8) {
        float tt = red[tid];
#pragma unroll
        for (int o = 4; o > 0; o >>= 1) tt = fmaxf(tt, __shfl_xor_sync(0xffu, tt, o));
        if (tid == 0) red[0] = tt;
    }
    __syncthreads();
    m = red[0];
    __syncthreads();

    v.x = expf(v.x - m); v.y = expf(v.y - m);
    v.z = expf(v.z - m); v.w = expf(v.w - m);
    float s = v.x + v.y + v.z + v.w;
#pragma unroll
    for (int o = 16; o > 0; o >>= 1) s += __shfl_xor_sync(0xffffffffu, s, o);
    if ((tid & 31) == 0) red[tid >> 5] = s;
    __syncthreads();
    if (tid < 8) {
        float tt = red[tid];
#pragma unroll
        for (int o = 4; o > 0; o >>= 1) tt += __shfl_xor_sync(0xffu, tt, o);
        if (tid == 0) red[0] = tt;
    }
    __syncthreads();
    float inv = 1.f / red[0];

    v.x *= inv; v.y *= inv; v.z *= inv; v.w *= inv;
    *reinterpret_cast<float4*>(p + tid * 4) = v;
}

// ---------------------------------------------------------------------------
// Launch
// ---------------------------------------------------------------------------
extern "C" void kernel_launch(void* const* d_in, const int* in_sizes, int n_in,
                              void* d_out, int out_size)
{
    const float* x       = (const float*)d_in[0];  // [T,B,F]
    const float* mask    = (const float*)d_in[1];  // [T,B]
    const float* W_in    = (const float*)d_in[2];  // [F,4U]
    const float* W_rec   = (const float*)d_in[3];  // [U,4U]
    const float* b_lstm  = (const float*)d_in[4];  // [4U]
    const float* W_dense = (const float*)d_in[5];  // [U,CODES]
    const float* b_dense = (const float*)d_in[6];  // [CODES]
    float* out = (float*)d_out;                    // [T,B,CODES]

    (void)in_sizes; (void)n_in; (void)out_size;

    const int smem_bytes = 512 * NU * 16 + 2 * B_ * PS * 4;  // 32KB + 132KB
    cudaFuncSetAttribute(lstm_persistent_kernel,
                         cudaFuncAttributeMaxDynamicSharedMemorySize, smem_bytes);

    // 0) reset sw barrier
    init_kernel<<<1, 32>>>();

    // 1) xz = x @ W_in + b_lstm : [T*B, 4U]
    {
        dim3 grid(G_ / 128, (T_ * B_) / 128);
        sgemm_db_kernel<0><<<grid, 256>>>(x, W_in, b_lstm, nullptr,
                                          T_ * B_, G_, F_);
    }

    // 2) full recurrence in one persistent kernel
    lstm_persistent_kernel<<<NBLK, 256, smem_bytes>>>(W_rec, mask);

    // 3) logits = relu(hseq_masked @ W_dense + b_dense) -> d_out
    {
        dim3 grid(CODES_ / 128, (T_ * B_) / 128);
        sgemm_db_kernel<1><<<grid, 256>>>(nullptr, W_dense, b_dense, out,
                                          T_ * B_, CODES_, U_);
    }

    // 4) softmax in place on d_out
    softmax1024_kernel<<<T_ * B_, 256>>>(out);
}

// round 10
// speedup vs baseline: 2.9345x; 1.2944x over previous
#include <cuda_runtime.h>
#include <cuda_bf16.h>
#include <cstdint>
#include <stdint.h>
#include <math.h>

// Problem constants
#define T_ 256
#define B_ 128
#define F_ 1024
#define U_ 512
#define G_ 2048   // 4*U
#define CODES_ 1024

// Persistent-LSTM config
#define NBLK 128
#define NU 4
#define KC 128
#define PS 132

// Scratch in __device__ globals (no runtime allocation allowed)
__device__ float g_xz[(long long)T_ * B_ * G_];     // 256 MiB
__device__ float g_hseq[(long long)T_ * B_ * U_];   // 64 MiB
__device__ float g_h[2][B_ * U_];
__device__ unsigned g_barcnt;

// bf16 hi/lo split operands for tensor-core GEMMs
__device__ __nv_bfloat16 g_xhi[(long long)T_ * B_ * F_];
__device__ __nv_bfloat16 g_xlo[(long long)T_ * B_ * F_];
__device__ __nv_bfloat16 g_hshi[(long long)T_ * B_ * U_];
__device__ __nv_bfloat16 g_hslo[(long long)T_ * B_ * U_];
__device__ __nv_bfloat16 g_withi[(long long)G_ * F_];       // W_in^T  [2048][1024]
__device__ __nv_bfloat16 g_witlo[(long long)G_ * F_];
__device__ __nv_bfloat16 g_wdthi[(long long)CODES_ * U_];   // W_dense^T [1024][512]
__device__ __nv_bfloat16 g_wdtlo[(long long)CODES_ * U_];

__device__ __forceinline__ unsigned smem_u32(const void* p) {
    return (unsigned)__cvta_generic_to_shared(p);
}

// ldmatrix x4 (non-transposed, b16)
__device__ __forceinline__ void ldsm_x4(uint32_t (&r)[4], uint32_t addr) {
    asm volatile("ldmatrix.sync.aligned.m8n8.x4.shared.b16 {%0,%1,%2,%3}, [%4];"
                 : "=r"(r[0]), "=r"(r[1]), "=r"(r[2]), "=r"(r[3]) : "r"(addr));
}

// m16n8k16 bf16 mma, fp32 accumulate
__device__ __forceinline__ void mma_bf16(float (&c)[4], const uint32_t (&a)[4],
                                         const uint32_t* b) {
    asm volatile(
        "mma.sync.aligned.m16n8k16.row.col.f32.bf16.bf16.f32 "
        "{%0,%1,%2,%3}, {%4,%5,%6,%7}, {%8,%9}, {%0,%1,%2,%3};"
        : "+f"(c[0]), "+f"(c[1]), "+f"(c[2]), "+f"(c[3])
        : "r"(a[0]), "r"(a[1]), "r"(a[2]), "r"(a[3]), "r"(b[0]), "r"(b[1]));
}

// ---------------------------------------------------------------------------
__global__ void init_kernel() {
    if (blockIdx.x == 0 && threadIdx.x == 0) g_barcnt = 0u;
}

// ---------------------------------------------------------------------------
// fp32 -> bf16 hi/lo split. DST 0: x -> g_xhi/g_xlo; DST 1: g_hseq -> g_hshi/lo
// ---------------------------------------------------------------------------
template <int DST>
__global__ __launch_bounds__(256) void cvt_split_kernel(const float* __restrict__ in,
                                                        long long n)
{
    const float* src = (DST == 0) ? in : (const float*)g_hseq;
    __nv_bfloat16* hi = (DST == 0) ? g_xhi : g_hshi;
    __nv_bfloat16* lo = (DST == 0) ? g_xlo : g_hslo;
    long long i = ((long long)blockIdx.x * 256 + threadIdx.x) * 4;
    if (i + 3 < n) {
        float4 v = *reinterpret_cast<const float4*>(src + i);
        __nv_bfloat16 h0 = __float2bfloat16(v.x);
        __nv_bfloat16 h1 = __float2bfloat16(v.y);
        __nv_bfloat16 h2 = __float2bfloat16(v.z);
        __nv_bfloat16 h3 = __float2bfloat16(v.w);
        hi[i + 0] = h0; hi[i + 1] = h1; hi[i + 2] = h2; hi[i + 3] = h3;
        lo[i + 0] = __float2bfloat16(v.x - __bfloat162float(h0));
        lo[i + 1] = __float2bfloat16(v.y - __bfloat162float(h1));
        lo[i + 2] = __float2bfloat16(v.z - __bfloat162float(h2));
        lo[i + 3] = __float2bfloat16(v.w - __bfloat162float(h3));
    }
}

// ---------------------------------------------------------------------------
// Transpose + split: in [K][N] fp32 -> out [N][K] bf16 hi/lo.
// ---------------------------------------------------------------------------
template <int DST>
__global__ __launch_bounds__(256) void cvt_transpose_kernel(const float* __restrict__ in,
                                                            int K, int N)
{
    __nv_bfloat16* hi = (DST == 0) ? g_withi : g_wdthi;
    __nv_bfloat16* lo = (DST == 0) ? g_witlo : g_wdtlo;
    __shared__ float t[32][33];
    int tx = threadIdx.x, ty = threadIdx.y;   // (32, 8)
    int bx = blockIdx.x, by = blockIdx.y;     // bx over N/32, by over K/32
#pragma unroll
    for (int j = 0; j < 4; j++) {
        int k = by * 32 + ty + j * 8;
        t[ty + j * 8][tx] = in[(long long)k * N + bx * 32 + tx];
    }
    __syncthreads();
#pragma unroll
    for (int j = 0; j < 4; j++) {
        int n = bx * 32 + ty + j * 8;
        int k = by * 32 + tx;
        float v = t[tx][ty + j * 8];
        __nv_bfloat16 h = __float2bfloat16(v);
        hi[(long long)n * K + k] = h;
        lo[(long long)n * K + k] = __float2bfloat16(v - __bfloat162float(h));
    }
}

// ---------------------------------------------------------------------------
// mma.sync bf16 3-pass GEMM: C[M,N] = A[M,K] @ B^T   (B stored [N][K] bf16)
// D = Ahi*Bhi + Ahi*Blo + Alo*Bhi, fp32 accum in registers.
// Block tile 128x128, 8 warps (2x4), warp tile 64x32, k-chunk 32, double-buffered.
// Smem per buffer: 4 sub-tiles [128][40] bf16 (padded 80B rows) = 40960 B; x2 = 81920 B.
// MODE 0: A=g_x{hi,lo}, B=g_wit{hi,lo}, C=g_xz, no ReLU
// MODE 1: A=g_hs{hi,lo}, B=g_wdt{hi,lo}, C=param, ReLU
// ---------------------------------------------------------------------------
#define MMT_BUF 40960u
#define MMT_SMEM (2 * 40960)

template <int MODE>
__global__ void __launch_bounds__(256, 1)
mmt_kernel(const float* __restrict__ bias, float* __restrict__ Cout, int N, int K)
{
    const __nv_bfloat16* Ahi = (MODE == 0) ? g_xhi  : g_hshi;
    const __nv_bfloat16* Alo = (MODE == 0) ? g_xlo  : g_hslo;
    const __nv_bfloat16* Bhi = (MODE == 0) ? g_withi : g_wdthi;
    const __nv_bfloat16* Blo = (MODE == 0) ? g_witlo : g_wdtlo;
    float* C = (MODE == 0) ? g_xz : Cout;

    extern __shared__ char smem_raw[];
    const uint32_t sbase = smem_u32(smem_raw);

    const int tid  = threadIdx.x;
    const int warp = tid >> 5;
    const int lane = tid & 31;
    const int wm = warp >> 2;     // 0..1 (m)
    const int wn = warp & 3;      // 0..3 (n)

    const long long aRowBase = (long long)blockIdx.y * 128;
    const long long bRowBase = (long long)blockIdx.x * 128;
    const int NC = K / 32;

    float acc[4][4][4];
#pragma unroll
    for (int mt = 0; mt < 4; mt++)
#pragma unroll
        for (int nt = 0; nt < 4; nt++)
#pragma unroll
            for (int q = 0; q < 4; q++) acc[mt][nt][q] = 0.f;

    // ---- chunk loader: 128 rows x 32 bf16 per sub-tile, 4 sub-tiles ----
    auto load_chunk = [&](int c, int b) {
        const long long kOff = (long long)c * 32;
#pragma unroll
        for (int i = 0; i < 2; i++) {
            int s = tid + i * 256;       // 0..511
            int row = s >> 2;            // 0..127
            int sc  = s & 3;             // 16B segment (8 bf16)
            uint32_t so = (uint32_t)b * MMT_BUF + (uint32_t)row * 80u + (uint32_t)sc * 16u;
            const __nv_bfloat16* pa = Ahi + (aRowBase + row) * (long long)K + kOff + sc * 8;
            const __nv_bfloat16* pl = Alo + (aRowBase + row) * (long long)K + kOff + sc * 8;
            const __nv_bfloat16* pb = Bhi + (bRowBase + row) * (long long)K + kOff + sc * 8;
            const __nv_bfloat16* pm = Blo + (bRowBase + row) * (long long)K + kOff + sc * 8;
            asm volatile("cp.async.cg.shared.global [%0], [%1], 16;\n" :: "r"(sbase + so),           "l"(pa));
            asm volatile("cp.async.cg.shared.global [%0], [%1], 16;\n" :: "r"(sbase + so + 10240u), "l"(pl));
            asm volatile("cp.async.cg.shared.global [%0], [%1], 16;\n" :: "r"(sbase + so + 20480u), "l"(pb));
            asm volatile("cp.async.cg.shared.global [%0], [%1], 16;\n" :: "r"(sbase + so + 30720u), "l"(pm));
        }
        asm volatile("cp.async.commit_group;\n");
    };

    // ---- compute on buffer b ----
    auto compute = [&](int b) {
        const uint32_t aHiB = sbase + (uint32_t)b * MMT_BUF;
        const uint32_t aLoB = aHiB + 10240u;
        const uint32_t bHiB = aHiB + 20480u;
        const uint32_t bLoB = aHiB + 30720u;
        // A ldmatrix lane addressing: row=(lane&15), k-half=(lane>>4)*8 elems
        const uint32_t aoff = (uint32_t)((wm * 64 + (lane & 15)) * 80) +
                              (uint32_t)((lane >> 4) * 16);
        // B ldmatrix lane addressing: n=(lane>>4)*8+(lane&7), k-half=((lane>>3)&1)*8 elems
        const uint32_t boff = (uint32_t)((wn * 32 + (lane >> 4) * 8 + (lane & 7)) * 80) +
                              (uint32_t)(((lane >> 3) & 1) * 16);
#pragma unroll
        for (int kt = 0; kt < 2; kt++) {
            const uint32_t kb = (uint32_t)(kt * 32);  // 16 bf16 = 32 bytes
            uint32_t ahi[4][4], alo[4][4], bhi[2][4], blo[2][4];
#pragma unroll
            for (int mt = 0; mt < 4; mt++) {
                ldsm_x4(ahi[mt], aHiB + aoff + (uint32_t)(mt * 16 * 80) + kb);
                ldsm_x4(alo[mt], aLoB + aoff + (uint32_t)(mt * 16 * 80) + kb);
            }
#pragma unroll
            for (int np = 0; np < 2; np++) {
                ldsm_x4(bhi[np], bHiB + boff + (uint32_t)(np * 16 * 80) + kb);
                ldsm_x4(blo[np], bLoB + boff + (uint32_t)(np * 16 * 80) + kb);
            }
#pragma unroll
            for (int mt = 0; mt < 4; mt++)
#pragma unroll
                for (int nt = 0; nt < 4; nt++) {
                    const uint32_t* bh = &bhi[nt >> 1][(nt & 1) * 2];
                    const uint32_t* bl = &blo[nt >> 1][(nt & 1) * 2];
                    mma_bf16(acc[mt][nt], ahi[mt], bh);
                    mma_bf16(acc[mt][nt], ahi[mt], bl);
                    mma_bf16(acc[mt][nt], alo[mt], bh);
                }
        }
    };

    // ---- main loop (double-buffered) ----
    load_chunk(0, 0);
    for (int c = 0; c < NC; c++) {
        const int cur = c & 1;
        if (c + 1 < NC) {
            load_chunk(c + 1, cur ^ 1);
            asm volatile("cp.async.wait_group 1;\n" ::: "memory");
        } else {
            asm volatile("cp.async.wait_group 0;\n" ::: "memory");
        }
        __syncthreads();
        compute(cur);
        __syncthreads();
    }

    // ---- epilogue: fragment -> global with bias (+ReLU) ----
    const int colBase = blockIdx.x * 128;
#pragma unroll
    for (int mt = 0; mt < 4; mt++) {
#pragma unroll
        for (int nt = 0; nt < 4; nt++) {
            int col = colBase + wn * 32 + nt * 8 + (lane & 3) * 2;
            long long row0 = aRowBase + wm * 64 + mt * 16 + (lane >> 2);
            float b0v = bias[col], b1v = bias[col + 1];
            float2 v0, v1;
            v0.x = acc[mt][nt][0] + b0v; v0.y = acc[mt][nt][1] + b1v;
            v1.x = acc[mt][nt][2] + b0v; v1.y = acc[mt][nt][3] + b1v;
            if (MODE == 1) {
                v0.x = fmaxf(v0.x, 0.f); v0.y = fmaxf(v0.y, 0.f);
                v1.x = fmaxf(v1.x, 0.f); v1.y = fmaxf(v1.y, 0.f);
            }
            *reinterpret_cast<float2*>(C + row0 * N + col) = v0;
            *reinterpret_cast<float2*>(C + (row0 + 8) * N + col) = v1;
        }
    }
}

// ---------------------------------------------------------------------------
// Persistent LSTM (UNCHANGED from R6 passing version)
// ---------------------------------------------------------------------------
__global__ void __launch_bounds__(256, 1)
lstm_persistent_kernel(const float* __restrict__ W_rec,
                       const float* __restrict__ mask)
{
    extern __shared__ char smem_raw[];
    float4* w_s = (float4*)smem_raw;                       // 512*NU float4 = 32KB
    float*  sh_h = (float*)(smem_raw + 512 * NU * 16);     // 2 * 128*PS floats

    const int tid = threadIdx.x;
    const int ul  = tid & (NU - 1);
    const int bp  = tid >> 2;
    const int b0  = bp * 2;
    const int b1  = bp * 2 + 1;
    const int u   = blockIdx.x * NU + ul;

    for (int idx = tid; idx < 512 * NU; idx += 256) {
        int k  = idx >> 2;
        int uu = blockIdx.x * NU + (idx & (NU - 1));
        const float* wr = W_rec + (long long)k * G_ + uu;
        float4 wv;
        wv.x = wr[0];
        wv.y = wr[U_];
        wv.z = wr[2 * U_];
        wv.w = wr[3 * U_];
        w_s[idx] = wv;
    }
    __syncthreads();

    float c0 = 0.f, c1 = 0.f;

    for (int t = 0; t < T_; t++) {
        const int p = t & 1;
        const float* __restrict__ h_in  = g_h[p];
        float* __restrict__       h_out = g_h[p ^ 1];
        const float* __restrict__ xz_t  = g_xz + (long long)t * B_ * G_;

        float a0, a1, a2, a3, a4, a5, a6, a7;
        {
            const long long base0 = (long long)b0 * G_ + u;
            const long long base1 = (long long)b1 * G_ + u;
            a0 = xz_t[base0];
            a1 = xz_t[base0 + U_];
            a2 = xz_t[base0 + 2 * U_];
            a3 = xz_t[base0 + 3 * U_];
            a4 = xz_t[base1];
            a5 = xz_t[base1 + U_];
            a6 = xz_t[base1 + 2 * U_];
            a7 = xz_t[base1 + 3 * U_];
        }

        if (t > 0) {
            {
                float* dst = sh_h;
#pragma unroll
                for (int i = 0; i < 16; i++) {
                    int idx = tid + i * 256;
                    int row = idx >> 5;
                    int ch  = idx & 31;
                    unsigned sa = smem_u32(dst + row * PS + ch * 4);
                    const float* gs = h_in + row * U_ + ch * 4;
                    asm volatile("cp.async.cg.shared.global [%0], [%1], 16;\n"
                                 :: "r"(sa), "l"(gs));
                }
                asm volatile("cp.async.commit_group;\n");
            }

#pragma unroll
            for (int cc = 0; cc < 4; cc++) {
                if (cc < 3) {
                    float* dst = sh_h + ((cc + 1) & 1) * (B_ * PS);
                    const int k0n = (cc + 1) * KC;
#pragma unroll
                    for (int i = 0; i < 16; i++) {
                        int idx = tid + i * 256;
                        int row = idx >> 5;
                        int ch  = idx & 31;
                        unsigned sa = smem_u32(dst + row * PS + ch * 4);
                        const float* gs = h_in + row * U_ + k0n + ch * 4;
                        asm volatile("cp.async.cg.shared.global [%0], [%1], 16;\n"
                                     :: "r"(sa), "l"(gs));
                    }
                    asm volatile("cp.async.commit_group;\n");
                    asm volatile("cp.async.wait_group 1;\n" ::: "memory");
                } else {
                    asm volatile("cp.async.wait_group 0;\n" ::: "memory");
                }
                __syncthreads();

                const float* shb = sh_h + (cc & 1) * (B_ * PS);
                const int k0 = cc * KC;
#pragma unroll 4
                for (int kk = 0; kk < KC; kk++) {
                    float h0 = shb[b0 * PS + kk];
                    float h1 = shb[b1 * PS + kk];
                    float4 wv = w_s[(k0 + kk) * NU + ul];
                    a0 = fmaf(h0, wv.x, a0);
                    a1 = fmaf(h0, wv.y, a1);
                    a2 = fmaf(h0, wv.z, a2);
                    a3 = fmaf(h0, wv.w, a3);
                    a4 = fmaf(h1, wv.x, a4);
                    a5 = fmaf(h1, wv.y, a5);
                    a6 = fmaf(h1, wv.z, a6);
                    a7 = fmaf(h1, wv.w, a7);
                }
                __syncthreads();
            }
        }

        float ig0 = 1.f / (1.f + expf(-a0));
        float fg0 = 1.f / (1.f + expf(-a1));
        float gg0 = tanhf(a2);
        float og0 = 1.f / (1.f + expf(-a3));
        c0 = fg0 * c0 + ig0 * gg0;
        float h0v = og0 * tanhf(c0);

        float ig1 = 1.f / (1.f + expf(-a4));
        float fg1 = 1.f / (1.f + expf(-a5));
        float gg1 = tanhf(a6);
        float og1 = 1.f / (1.f + expf(-a7));
        c1 = fg1 * c1 + ig1 * gg1;
        float h1v = og1 * tanhf(c1);

        h_out[b0 * U_ + u] = h0v;
        h_out[b1 * U_ + u] = h1v;

        float m0 = mask[t * B_ + b0];
        float m1 = mask[t * B_ + b1];
        float* hs = g_hseq + (long long)t * B_ * U_;
        hs[b0 * U_ + u] = h0v * m0;
        hs[b1 * U_ + u] = h1v * m1;

        if (t < T_ - 1) {
            __threadfence();
            __syncthreads();
            if (tid == 0) {
                atomicAdd(&g_barcnt, 1u);
                const unsigned target = (unsigned)(t + 1) * (unsigned)gridDim.x;
                while (*((volatile unsigned*)&g_barcnt) < target) { }
                __threadfence();
            }
            __syncthreads();
        }
    }
}

// ---------------------------------------------------------------------------
// In-place softmax over rows of 1024. One block per row. (UNCHANGED)
// ---------------------------------------------------------------------------
__global__ __launch_bounds__(256) void softmax1024_kernel(float* __restrict__ data)
{
    __shared__ float red[32];
    long long row = blockIdx.x;
    float* p = data + row * CODES_;
    int tid = threadIdx.x;

    float4 v = *reinterpret_cast<const float4*>(p + tid * 4);

    float m = fmaxf(fmaxf(v.x, v.y), fmaxf(v.z, v.w));
#pragma unroll
    for (int o = 16; o > 0; o >>= 1) m = fmaxf(m, __shfl_xor_sync(0xffffffffu, m, o));
    if ((tid & 31) == 0) red[tid >> 5] = m;
    __syncthreads();
    if (tid < 8) {
        float tt = red[tid];
#pragma unroll
        for (int o = 4; o > 0; o >>= 1) tt = fmaxf(tt, __shfl_xor_sync(0xffu, tt, o));
        if (tid == 0) red[0] = tt;
    }
    __syncthreads();
    m = red[0];
    __syncthreads();

    v.x = expf(v.x - m); v.y = expf(v.y - m);
    v.z = expf(v.z - m); v.w = expf(v.w - m);
    float s = v.x + v.y + v.z + v.w;
#pragma unroll
    for (int o = 16; o > 0; o >>= 1) s += __shfl_xor_sync(0xffffffffu, s, o);
    if ((tid & 31) == 0) red[tid >> 5] = s;
    __syncthreads();
    if (tid < 8) {
        float tt = red[tid];
#pragma unroll
        for (int o = 4; o > 0; o >>= 1) tt += __shfl_xor_sync(0xffu, tt, o);
        if (tid == 0) red[0] = tt;
    }
    __syncthreads();
    float inv = 1.f / red[0];

    v.x *= inv; v.y *= inv; v.z *= inv; v.w *= inv;
    *reinterpret_cast<float4*>(p + tid * 4) = v;
}

// ---------------------------------------------------------------------------
// Launch
// ---------------------------------------------------------------------------
extern "C" void kernel_launch(void* const* d_in, const int* in_sizes, int n_in,
                              void* d_out, int out_size)
{
    const float* x       = (const float*)d_in[0];  // [T,B,F]
    const float* mask    = (const float*)d_in[1];  // [T,B]
    const float* W_in    = (const float*)d_in[2];  // [F,4U]
    const float* W_rec   = (const float*)d_in[3];  // [U,4U]
    const float* b_lstm  = (const float*)d_in[4];  // [4U]
    const float* W_dense = (const float*)d_in[5];  // [U,CODES]
    const float* b_dense = (const float*)d_in[6];  // [CODES]
    float* out = (float*)d_out;                    // [T,B,CODES]

    (void)in_sizes; (void)n_in; (void)out_size;

    const int lstm_smem = 512 * NU * 16 + 2 * B_ * PS * 4;
    cudaFuncSetAttribute(lstm_persistent_kernel,
                         cudaFuncAttributeMaxDynamicSharedMemorySize, lstm_smem);
    cudaFuncSetAttribute(mmt_kernel<0>,
                         cudaFuncAttributeMaxDynamicSharedMemorySize, MMT_SMEM);
    cudaFuncSetAttribute(mmt_kernel<1>,
                         cudaFuncAttributeMaxDynamicSharedMemorySize, MMT_SMEM);

    // 0) reset sw barrier
    init_kernel<<<1, 32>>>();

    // 1) split x into bf16 hi/lo; transpose+split W_in
    {
        long long n = (long long)T_ * B_ * F_;
        cvt_split_kernel<0><<<(unsigned)(n / 4 / 256), 256>>>(x, n);
        cvt_transpose_kernel<0><<<dim3(G_ / 32, F_ / 32), dim3(32, 8)>>>(W_in, F_, G_);
    }

    // 2) xz = x @ W_in + b_lstm  (mma.sync bf16 3-pass)
    mmt_kernel<0><<<dim3(G_ / 128, (T_ * B_) / 128), 256, MMT_SMEM>>>(
        b_lstm, nullptr, G_, F_);

    // 3) recurrence
    lstm_persistent_kernel<<<NBLK, 256, lstm_smem>>>(W_rec, mask);

    // 4) split hseq; transpose+split W_dense
    {
        long long n = (long long)T_ * B_ * U_;
        cvt_split_kernel<1><<<(unsigned)(n / 4 / 256), 256>>>(nullptr, n);
        cvt_transpose_kernel<1><<<dim3(CODES_ / 32, U_ / 32), dim3(32, 8)>>>(W_dense, U_, CODES_);
    }

    // 5) logits = relu(hseq @ W_dense + b_dense) -> out (mma.sync bf16 3-pass)
    mmt_kernel<1><<<dim3(CODES_ / 128, (T_ * B_) / 128), 256, MMT_SMEM>>>(
        b_dense, out, CODES_, U_);

    // 6) softmax in place
    softmax1024_kernel<<<T_ * B_, 256>>>(out);
}